// round 11
// baseline (speedup 1.0000x reference)
#include <cuda_runtime.h>
#include <cuda_fp16.h>
#include <stdint.h>

#define DIM   64
#define MAX_N 150016           // 100000 users + 50000 items, padded
#define MAX_E 1300000          // actual E = 1,200,000 (incl. flipped copy)

#define SCAN_TB    256
#define SCAN_ITEMS 8           // 2048 elements per block
#define SCAN_CHUNK (SCAN_TB * SCAN_ITEMS)
#define MAX_SCAN_BLOCKS 512

// ---------------------------------------------------------------------------
// Scratch: __device__ globals only (no allocations allowed anywhere).
// Ping-pong buffers hold w = dinv .* x in fp16; a node row is 8 uint4 chunks
// (8 lanes x 16 B = 128 B contiguous).
// ---------------------------------------------------------------------------
__device__ uint4  g_bufA[MAX_N * 8];     // ping (w0, then w2)
__device__ uint4  g_bufB[MAX_N * 8];     // pong (w1)
__device__ float4 g_dinvs[MAX_N];        // (dinv, dinv^2, sqrt(deg), 0); 0s if isolated
__device__ int    g_counts[MAX_N];       // degree histogram
__device__ int    g_offsets[MAX_N + 1];  // CSR row pointers (by dst)
__device__ int    g_pos[MAX_N];          // scatter cursors
__device__ int    g_src[MAX_E];          // CSR: source node per slot
__device__ int    g_blocksums[MAX_SCAN_BLOCKS];

// ---------------------------------------------------------------------------
// 1) histogram of destinations (full edge list)
// ---------------------------------------------------------------------------
__global__ void zero_counts_kernel(int n) {
    int i = blockIdx.x * blockDim.x + threadIdx.x;
    if (i < n) g_counts[i] = 0;
}

__global__ void count_kernel(const int* __restrict__ edge, int E) {
    int e = blockIdx.x * blockDim.x + threadIdx.x;
    if (e < E) atomicAdd(&g_counts[edge[E + e]], 1);
}

// ---------------------------------------------------------------------------
// 2) scan, phase A: per-block partial sums of counts. Also emits g_dinvs
//    (fused — counts are already streaming through this kernel).
// ---------------------------------------------------------------------------
__global__ __launch_bounds__(SCAN_TB)
void scan_partial_kernel(int n) {
    __shared__ int warp_sums[SCAN_TB / 32];
    const int base = blockIdx.x * SCAN_CHUNK;
    const int t = threadIdx.x;

    int s = 0;
    #pragma unroll
    for (int i = 0; i < SCAN_ITEMS; i++) {
        int idx = base + i * SCAN_TB + t;       // coalesced
        if (idx < n) {
            int c = g_counts[idx];
            s += c;
            float d  = (c > 0) ? rsqrtf((float)c) : 0.0f;
            float sd = (c > 0) ? sqrtf((float)c)  : 0.0f;
            g_dinvs[idx] = make_float4(d, d * d, sd, 0.0f);
        }
    }
    #pragma unroll
    for (int o = 16; o > 0; o >>= 1) s += __shfl_down_sync(0xffffffffu, s, o);
    if ((t & 31) == 0) warp_sums[t >> 5] = s;
    __syncthreads();
    if (t < SCAN_TB / 32) {
        int v = warp_sums[t];
        #pragma unroll
        for (int o = SCAN_TB / 64; o > 0; o >>= 1) v += __shfl_down_sync(0xffffffffu, v, o);
        if (t == 0) g_blocksums[blockIdx.x] = v;
    }
}

// ---------------------------------------------------------------------------
// 2) scan, phase B: per-block local exclusive scan; the block offset is
//    computed in-kernel by warp 0 summing all preceding blocksums (<= 74 ints
//    — cheaper than a dedicated single-block scan kernel + launch bubble).
// ---------------------------------------------------------------------------
__global__ __launch_bounds__(SCAN_TB)
void scan_write_kernel(int n, int E) {
    __shared__ int thread_sums[SCAN_TB];
    __shared__ int block_off;
    const int base = blockIdx.x * SCAN_CHUNK;
    const int t = threadIdx.x;
    const int lo = base + t * SCAN_ITEMS;

    // warp 0: exclusive prefix of blocksums up to this block
    if (t < 32) {
        int s = 0;
        for (int i = t; i < blockIdx.x; i += 32) s += g_blocksums[i];
        #pragma unroll
        for (int o = 16; o > 0; o >>= 1) s += __shfl_down_sync(0xffffffffu, s, o);
        if (t == 0) block_off = s;
    }

    int c[SCAN_ITEMS];
    int s = 0;
    #pragma unroll
    for (int i = 0; i < SCAN_ITEMS; i++) {
        int idx = lo + i;
        c[i] = (idx < n) ? g_counts[idx] : 0;
        s += c[i];
    }
    thread_sums[t] = s;
    __syncthreads();
    #pragma unroll
    for (int off = 1; off < SCAN_TB; off <<= 1) {
        int v = (t >= off) ? thread_sums[t - off] : 0;
        __syncthreads();
        thread_sums[t] += v;
        __syncthreads();
    }
    int prefix = block_off + ((t == 0) ? 0 : thread_sums[t - 1]);
    #pragma unroll
    for (int i = 0; i < SCAN_ITEMS; i++) {
        int idx = lo + i;
        if (idx < n) {
            g_offsets[idx] = prefix;
            g_pos[idx]     = prefix;
            prefix += c[i];
        }
    }
    if (blockIdx.x == gridDim.x - 1 && t == SCAN_TB - 1) g_offsets[n] = E;
}

// ---------------------------------------------------------------------------
// 3) scatter edges into CSR slots (full edge list)
// ---------------------------------------------------------------------------
__global__ void fill_kernel(const int* __restrict__ edge, int E) {
    int e = blockIdx.x * blockDim.x + threadIdx.x;
    if (e >= E) return;
    int r = edge[e];
    int c = edge[E + e];
    int slot = atomicAdd(&g_pos[c], 1);
    g_src[slot] = r;
}

// ---------------------------------------------------------------------------
// 4) init: A = w0 = fp16(dinv .* x0)   (out deferred to last pull)
// ---------------------------------------------------------------------------
__global__ void init_kernel(const float* __restrict__ ue, const float* __restrict__ ie,
                            int nu_elems, int total) {
    int i = blockIdx.x * blockDim.x + threadIdx.x;
    if (i < total) {
        float v = (i < nu_elems) ? ue[i] : ie[i - nu_elems];
        reinterpret_cast<__half*>(g_bufA)[i] = __float2half_rn(v * g_dinvs[i >> 6].x);
    }
}

// ---------------------------------------------------------------------------
// 5) pull pass: S[n] = sum_{k in csr(n)} W[src[k]]  (fp16 payload, fp32 accum)
//    MID:  Y[n] = fp16( dinv^2 * S )
//    LAST: out[n] = 0.25*( x0 + sqrtdeg*(w1+w2) + dinv*S )
//    8 threads per node, one uint4 (8 halves = 16 B) lane each.
//    Software-pipelined 2-edge unroll: next pair's loads issue before the
//    current pair is consumed -> 4 gathers in flight per thread.
// ---------------------------------------------------------------------------
__device__ __forceinline__ void acc_u4(const uint4 u, float* a) {
    float2 f0 = __half22float2(*reinterpret_cast<const __half2*>(&u.x));
    float2 f1 = __half22float2(*reinterpret_cast<const __half2*>(&u.y));
    float2 f2 = __half22float2(*reinterpret_cast<const __half2*>(&u.z));
    float2 f3 = __half22float2(*reinterpret_cast<const __half2*>(&u.w));
    a[0] += f0.x; a[1] += f0.y; a[2] += f1.x; a[3] += f1.y;
    a[4] += f2.x; a[5] += f2.y; a[6] += f3.x; a[7] += f3.y;
}

template <bool A_TO_B, bool LAST>
__global__ __launch_bounds__(256)
void pull_kernel(int N, int nu_nodes,
                 const float* __restrict__ ue, const float* __restrict__ ie,
                 float* __restrict__ out) {
    int t = blockIdx.x * blockDim.x + threadIdx.x;
    int node = t >> 3;
    if (node >= N) return;
    int lane = t & 7;                       // dims [lane*8, lane*8+8)

    const uint4* __restrict__ X = A_TO_B ? g_bufA : g_bufB;
    uint4*       __restrict__ Y = A_TO_B ? g_bufB : g_bufA;

    const int beg = g_offsets[node];
    const int end = g_offsets[node + 1];

    float a0[8] = {0.f, 0.f, 0.f, 0.f, 0.f, 0.f, 0.f, 0.f};
    float a1[8] = {0.f, 0.f, 0.f, 0.f, 0.f, 0.f, 0.f, 0.f};

    int k = beg;
    if (k + 1 < end) {
        uint4 u0 = X[(size_t)g_src[k]     * 8 + lane];
        uint4 u1 = X[(size_t)g_src[k + 1] * 8 + lane];
        k += 2;
        for (; k + 1 < end; k += 2) {
            uint4 v0 = X[(size_t)g_src[k]     * 8 + lane];  // in flight while
            uint4 v1 = X[(size_t)g_src[k + 1] * 8 + lane];  // consuming u0/u1
            acc_u4(u0, a0);
            acc_u4(u1, a1);
            u0 = v0; u1 = v1;
        }
        acc_u4(u0, a0);
        acc_u4(u1, a1);
    }
    if (k < end) {
        uint4 u0 = X[(size_t)g_src[k] * 8 + lane];
        acc_u4(u0, a0);
    }

    float s[8];
    #pragma unroll
    for (int i = 0; i < 8; i++) s[i] = a0[i] + a1[i];

    float4 dv = g_dinvs[node];              // (dinv, dinv^2, sqrtdeg, 0)

    if (!LAST) {
        __half2 p0 = __floats2half2_rn(dv.y * s[0], dv.y * s[1]);
        __half2 p1 = __floats2half2_rn(dv.y * s[2], dv.y * s[3]);
        __half2 p2 = __floats2half2_rn(dv.y * s[4], dv.y * s[5]);
        __half2 p3 = __floats2half2_rn(dv.y * s[6], dv.y * s[7]);
        uint4 st;
        st.x = *reinterpret_cast<unsigned int*>(&p0);
        st.y = *reinterpret_cast<unsigned int*>(&p1);
        st.z = *reinterpret_cast<unsigned int*>(&p2);
        st.w = *reinterpret_cast<unsigned int*>(&p3);
        Y[(size_t)node * 8 + lane] = st;
    } else {
        // x0 from inputs; w1 in bufB, w2 in bufA (== X for this launch)
        const float* x0row = (node < nu_nodes)
            ? (ue + (size_t)node * DIM)
            : (ie + (size_t)(node - nu_nodes) * DIM);
        float4 x0a = *reinterpret_cast<const float4*>(x0row + (lane << 3));
        float4 x0b = *reinterpret_cast<const float4*>(x0row + (lane << 3) + 4);

        float w1[8] = {0.f, 0.f, 0.f, 0.f, 0.f, 0.f, 0.f, 0.f};
        float w2[8] = {0.f, 0.f, 0.f, 0.f, 0.f, 0.f, 0.f, 0.f};
        acc_u4(g_bufB[(size_t)node * 8 + lane], w1);
        acc_u4(g_bufA[(size_t)node * 8 + lane], w2);

        float4 ra, rb;
        ra.x = 0.25f * (x0a.x + dv.z * (w1[0] + w2[0]) + dv.x * s[0]);
        ra.y = 0.25f * (x0a.y + dv.z * (w1[1] + w2[1]) + dv.x * s[1]);
        ra.z = 0.25f * (x0a.z + dv.z * (w1[2] + w2[2]) + dv.x * s[2]);
        ra.w = 0.25f * (x0a.w + dv.z * (w1[3] + w2[3]) + dv.x * s[3]);
        rb.x = 0.25f * (x0b.x + dv.z * (w1[4] + w2[4]) + dv.x * s[4]);
        rb.y = 0.25f * (x0b.y + dv.z * (w1[5] + w2[5]) + dv.x * s[5]);
        rb.z = 0.25f * (x0b.z + dv.z * (w1[6] + w2[6]) + dv.x * s[6]);
        rb.w = 0.25f * (x0b.w + dv.z * (w1[7] + w2[7]) + dv.x * s[7]);

        float* orow = out + (size_t)node * DIM + (lane << 3);
        *reinterpret_cast<float4*>(orow)     = ra;
        *reinterpret_cast<float4*>(orow + 4) = rb;
    }
}

// ---------------------------------------------------------------------------
// kernel_launch
// inputs: [0] user_emb f32 [100000*64], [1] item_emb f32 [50000*64],
//         [2] edge_index int32 [2 * 1200000]
// output: f32 [150000*64]
// ---------------------------------------------------------------------------
extern "C" void kernel_launch(void* const* d_in, const int* in_sizes, int n_in,
                              void* d_out, int out_size) {
    const float* user_emb = (const float*)d_in[0];
    const float* item_emb = (const float*)d_in[1];
    const int*   edge     = (const int*)d_in[2];
    float*       out      = (float*)d_out;

    const int nu_elems = in_sizes[0];
    const int ni_elems = in_sizes[1];
    const int E        = in_sizes[2] / 2;
    const int NU       = nu_elems / DIM;
    const int N        = NU + ni_elems / DIM;
    const int total    = N * DIM;

    const int TB = 256;
    const int nblk  = (N + TB - 1) / TB;
    const int eblk  = (E + TB - 1) / TB;
    const int tblk  = (total + TB - 1) / TB;
    const int pullb = (N * 8 + TB - 1) / TB;
    const int scanb = (N + SCAN_CHUNK - 1) / SCAN_CHUNK;

    // CSR build (by destination) — 5 kernels
    zero_counts_kernel<<<nblk, TB>>>(N);
    count_kernel<<<eblk, TB>>>(edge, E);
    scan_partial_kernel<<<scanb, SCAN_TB>>>(N);      // + g_dinvs
    scan_write_kernel<<<scanb, SCAN_TB>>>(N, E);     // + in-kernel blocksum scan
    fill_kernel<<<eblk, TB>>>(edge, E);

    // w0 only (out deferred)
    init_kernel<<<tblk, TB>>>(user_emb, item_emb, nu_elems, total);

    // 3 propagation layers; out materialized only in the last one
    pull_kernel<true , false><<<pullb, TB>>>(N, NU, user_emb, item_emb, out); // A->B (w1)
    pull_kernel<false, false><<<pullb, TB>>>(N, NU, user_emb, item_emb, out); // B->A (w2)
    pull_kernel<true , true ><<<pullb, TB>>>(N, NU, user_emb, item_emb, out); // A-> out
}

// round 14
// speedup vs baseline: 1.0535x; 1.0535x over previous
#include <cuda_runtime.h>
#include <cuda_fp16.h>
#include <stdint.h>

#define DIM   64
#define MAX_N 150016           // 100000 users + 50000 items, padded
#define MAX_E 1300000          // actual E = 1,200,000 (incl. flipped copy)

#define SCAN_TB    256
#define SCAN_ITEMS 8           // 2048 elements per block
#define SCAN_CHUNK (SCAN_TB * SCAN_ITEMS)
#define MAX_SCAN_BLOCKS 512

// ---------------------------------------------------------------------------
// Scratch: __device__ globals only (no allocations allowed anywhere).
// Ping-pong buffers hold w = dinv .* x in fp16 (uint2 = 4 halves per lane;
// 16 lanes per 64-dim node row = 128 B contiguous).
// INVARIANT: g_counts == 0 between kernel_launch calls. It is zero-initialized
// at module load, and scan_write_kernel re-zeros every element after use, so
// the invariant holds on the first call and on every graph replay.
// ---------------------------------------------------------------------------
__device__ uint2  g_bufA[MAX_N * 16];    // ping (w0, then w2)
__device__ uint2  g_bufB[MAX_N * 16];    // pong (w1)
__device__ float4 g_dinvs[MAX_N];        // (dinv, dinv^2, sqrt(deg), 0); 0s if isolated
__device__ int    g_counts[MAX_N];       // degree histogram (zero between calls)
__device__ int    g_offsets[MAX_N + 1];  // CSR row pointers (by dst)
__device__ int    g_pos[MAX_N];          // scatter cursors
__device__ int    g_src[MAX_E];          // CSR: source node per slot
__device__ int    g_blocksums[MAX_SCAN_BLOCKS];
__device__ int    g_blockoffs[MAX_SCAN_BLOCKS];

// ---------------------------------------------------------------------------
// 1) histogram of destinations (counts are zero on entry per invariant)
// ---------------------------------------------------------------------------
__global__ void count_kernel(const int* __restrict__ edge, int E) {
    int e = blockIdx.x * blockDim.x + threadIdx.x;
    if (e < E) atomicAdd(&g_counts[edge[E + e]], 1);
}

// deg^{-1/2}, deg^{-1}, deg^{1/2}; zeros on isolated nodes (never gathered).
__global__ void dinv_kernel(int n) {
    int i = blockIdx.x * blockDim.x + threadIdx.x;
    if (i < n) {
        int c = g_counts[i];
        float d  = (c > 0) ? rsqrtf((float)c) : 0.0f;
        float sd = (c > 0) ? sqrtf((float)c)  : 0.0f;
        g_dinvs[i] = make_float4(d, d * d, sd, 0.0f);
    }
}

// ---------------------------------------------------------------------------
// 2) multi-block exclusive scan of counts -> offsets (3 phases)
// ---------------------------------------------------------------------------
__global__ __launch_bounds__(SCAN_TB)
void scan_partial_kernel(int n) {
    __shared__ int warp_sums[SCAN_TB / 32];
    const int base = blockIdx.x * SCAN_CHUNK;
    const int t = threadIdx.x;

    int s = 0;
    #pragma unroll
    for (int i = 0; i < SCAN_ITEMS; i++) {
        int idx = base + i * SCAN_TB + t;       // coalesced
        if (idx < n) s += g_counts[idx];
    }
    #pragma unroll
    for (int o = 16; o > 0; o >>= 1) s += __shfl_down_sync(0xffffffffu, s, o);
    if ((t & 31) == 0) warp_sums[t >> 5] = s;
    __syncthreads();
    if (t < SCAN_TB / 32) {
        int v = warp_sums[t];
        #pragma unroll
        for (int o = SCAN_TB / 64; o > 0; o >>= 1) v += __shfl_down_sync(0xffffffffu, v, o);
        if (t == 0) g_blocksums[blockIdx.x] = v;
    }
}

__global__ __launch_bounds__(MAX_SCAN_BLOCKS)
void scan_blocksums_kernel(int nb, int n, int E) {
    __shared__ int sh[MAX_SCAN_BLOCKS];
    const int t = threadIdx.x;
    sh[t] = (t < nb) ? g_blocksums[t] : 0;
    __syncthreads();
    #pragma unroll
    for (int off = 1; off < MAX_SCAN_BLOCKS; off <<= 1) {
        int v = (t >= off) ? sh[t - off] : 0;
        __syncthreads();
        sh[t] += v;
        __syncthreads();
    }
    if (t < nb) g_blockoffs[t] = (t == 0) ? 0 : sh[t - 1];
    if (t == 0) g_offsets[n] = E;
}

// Phase C also restores the g_counts == 0 invariant after consuming counts.
__global__ __launch_bounds__(SCAN_TB)
void scan_write_kernel(int n) {
    __shared__ int thread_sums[SCAN_TB];
    const int base = blockIdx.x * SCAN_CHUNK;
    const int t = threadIdx.x;
    const int lo = base + t * SCAN_ITEMS;

    int c[SCAN_ITEMS];
    int s = 0;
    #pragma unroll
    for (int i = 0; i < SCAN_ITEMS; i++) {
        int idx = lo + i;
        c[i] = (idx < n) ? g_counts[idx] : 0;
        s += c[i];
    }
    thread_sums[t] = s;
    __syncthreads();
    #pragma unroll
    for (int off = 1; off < SCAN_TB; off <<= 1) {
        int v = (t >= off) ? thread_sums[t - off] : 0;
        __syncthreads();
        thread_sums[t] += v;
        __syncthreads();
    }
    int prefix = g_blockoffs[blockIdx.x] + ((t == 0) ? 0 : thread_sums[t - 1]);
    #pragma unroll
    for (int i = 0; i < SCAN_ITEMS; i++) {
        int idx = lo + i;
        if (idx < n) {
            g_offsets[idx] = prefix;
            g_pos[idx]     = prefix;
            g_counts[idx]  = 0;                 // restore invariant for next call
            prefix += c[i];
        }
    }
}

// ---------------------------------------------------------------------------
// 3) scatter edges into CSR slots (full edge list)
// ---------------------------------------------------------------------------
__global__ void fill_kernel(const int* __restrict__ edge, int E) {
    int e = blockIdx.x * blockDim.x + threadIdx.x;
    if (e >= E) return;
    int r = edge[e];
    int c = edge[E + e];
    int slot = atomicAdd(&g_pos[c], 1);
    g_src[slot] = r;
}

// ---------------------------------------------------------------------------
// 4) init: A = w0 = fp16(dinv .* x0)   (out deferred to last pull)
// ---------------------------------------------------------------------------
__global__ void init_kernel(const float* __restrict__ ue, const float* __restrict__ ie,
                            int nu_elems, int total) {
    int i = blockIdx.x * blockDim.x + threadIdx.x;
    if (i < total) {
        float v = (i < nu_elems) ? ue[i] : ie[i - nu_elems];
        reinterpret_cast<__half*>(g_bufA)[i] = __float2half_rn(v * g_dinvs[i >> 6].x);
    }
}

// ---------------------------------------------------------------------------
// 5) pull pass: S[n] = sum_{k in csr(n)} W[src[k]]  (fp16 payload, fp32 accum)
//    MID:  Y[n] = fp16( dinv^2 * S )
//    LAST: out[n] = 0.25*( x0 + sqrtdeg*(w1+w2) + dinv*S )
//    16 threads (half-warp) per node, one uint2 (4 halves) lane each;
//    2-edge unroll with dual accumulators (proven R9 loop).
// ---------------------------------------------------------------------------
__device__ __forceinline__ void acc_u2(const uint2 u, float& x, float& y, float& z, float& w) {
    float2 f0 = __half22float2(*reinterpret_cast<const __half2*>(&u.x));
    float2 f1 = __half22float2(*reinterpret_cast<const __half2*>(&u.y));
    x += f0.x; y += f0.y; z += f1.x; w += f1.y;
}

template <bool A_TO_B, bool LAST>
__global__ __launch_bounds__(256)
void pull_kernel(int N, int nu_nodes,
                 const float* __restrict__ ue, const float* __restrict__ ie,
                 float* __restrict__ out) {
    int t = blockIdx.x * blockDim.x + threadIdx.x;
    int node = t >> 4;
    if (node >= N) return;
    int lane = t & 15;

    const uint2* __restrict__ X = A_TO_B ? g_bufA : g_bufB;
    uint2*       __restrict__ Y = A_TO_B ? g_bufB : g_bufA;

    const int beg = g_offsets[node];
    const int end = g_offsets[node + 1];

    float a0x = 0.f, a0y = 0.f, a0z = 0.f, a0w = 0.f;
    float a1x = 0.f, a1y = 0.f, a1z = 0.f, a1w = 0.f;

    int k = beg;
    for (; k + 1 < end; k += 2) {
        int s0 = g_src[k];
        int s1 = g_src[k + 1];
        uint2 u0 = X[(size_t)s0 * 16 + lane];
        uint2 u1 = X[(size_t)s1 * 16 + lane];
        acc_u2(u0, a0x, a0y, a0z, a0w);
        acc_u2(u1, a1x, a1y, a1z, a1w);
    }
    if (k < end) {
        uint2 u0 = X[(size_t)g_src[k] * 16 + lane];
        acc_u2(u0, a0x, a0y, a0z, a0w);
    }

    float sx = a0x + a1x, sy = a0y + a1y, sz = a0z + a1z, sw = a0w + a1w;

    float4 dv = g_dinvs[node];          // (dinv, dinv^2, sqrtdeg, 0)

    if (!LAST) {
        __half2 p0 = __floats2half2_rn(dv.y * sx, dv.y * sy);
        __half2 p1 = __floats2half2_rn(dv.y * sz, dv.y * sw);
        uint2 st;
        st.x = *reinterpret_cast<unsigned int*>(&p0);
        st.y = *reinterpret_cast<unsigned int*>(&p1);
        Y[(size_t)node * 16 + lane] = st;
    } else {
        // x0 from inputs; w1 in bufB, w2 in bufA (== X for this launch)
        const float* x0row = (node < nu_nodes)
            ? (ue + (size_t)node * DIM)
            : (ie + (size_t)(node - nu_nodes) * DIM);
        float4 x0 = *reinterpret_cast<const float4*>(x0row + (lane << 2));

        uint2 u1 = g_bufB[(size_t)node * 16 + lane];
        uint2 u2 = g_bufA[(size_t)node * 16 + lane];
        float w1x = 0.f, w1y = 0.f, w1z = 0.f, w1w = 0.f;
        float w2x = 0.f, w2y = 0.f, w2z = 0.f, w2w = 0.f;
        acc_u2(u1, w1x, w1y, w1z, w1w);
        acc_u2(u2, w2x, w2y, w2z, w2w);

        float4 r;
        r.x = 0.25f * (x0.x + dv.z * (w1x + w2x) + dv.x * sx);
        r.y = 0.25f * (x0.y + dv.z * (w1y + w2y) + dv.x * sy);
        r.z = 0.25f * (x0.z + dv.z * (w1z + w2z) + dv.x * sz);
        r.w = 0.25f * (x0.w + dv.z * (w1w + w2w) + dv.x * sw);
        *reinterpret_cast<float4*>(out + (size_t)node * DIM + (lane << 2)) = r;
    }
}

// ---------------------------------------------------------------------------
// kernel_launch
// inputs: [0] user_emb f32 [100000*64], [1] item_emb f32 [50000*64],
//         [2] edge_index int32 [2 * 1200000]
// output: f32 [150000*64]
// ---------------------------------------------------------------------------
extern "C" void kernel_launch(void* const* d_in, const int* in_sizes, int n_in,
                              void* d_out, int out_size) {
    const float* user_emb = (const float*)d_in[0];
    const float* item_emb = (const float*)d_in[1];
    const int*   edge     = (const int*)d_in[2];
    float*       out      = (float*)d_out;

    const int nu_elems = in_sizes[0];
    const int ni_elems = in_sizes[1];
    const int E        = in_sizes[2] / 2;
    const int NU       = nu_elems / DIM;
    const int N        = NU + ni_elems / DIM;
    const int total    = N * DIM;

    const int TB = 256;
    const int nblk  = (N + TB - 1) / TB;
    const int eblk  = (E + TB - 1) / TB;
    const int tblk  = (total + TB - 1) / TB;
    const int pullb = (N * 16 + TB - 1) / TB;
    const int scanb = (N + SCAN_CHUNK - 1) / SCAN_CHUNK;

    // CSR build (by destination); counts arrive zero per the self-clean invariant
    count_kernel<<<eblk, TB>>>(edge, E);
    dinv_kernel<<<nblk, TB>>>(N);
    scan_partial_kernel<<<scanb, SCAN_TB>>>(N);
    scan_blocksums_kernel<<<1, MAX_SCAN_BLOCKS>>>(scanb, N, E);
    scan_write_kernel<<<scanb, SCAN_TB>>>(N);
    fill_kernel<<<eblk, TB>>>(edge, E);

    // w0 only (out deferred)
    init_kernel<<<tblk, TB>>>(user_emb, item_emb, nu_elems, total);

    // 3 propagation layers; out materialized only in the last one
    pull_kernel<true , false><<<pullb, TB>>>(N, NU, user_emb, item_emb, out); // A->B (w1)
    pull_kernel<false, false><<<pullb, TB>>>(N, NU, user_emb, item_emb, out); // B->A (w2)
    pull_kernel<true , true ><<<pullb, TB>>>(N, NU, user_emb, item_emb, out); // A-> out
}

// round 15
// speedup vs baseline: 1.0730x; 1.0185x over previous
#include <cuda_runtime.h>
#include <cuda_fp16.h>
#include <stdint.h>

#define DIM   64
#define MAX_N 150016           // 100000 users + 50000 items, padded
#define MAX_E 1300000          // actual E = 1,200,000 (incl. flipped copy)

#define SCAN_TB    256
#define SCAN_ITEMS 8           // 2048 elements per block
#define SCAN_CHUNK (SCAN_TB * SCAN_ITEMS)
#define MAX_SCAN_BLOCKS 512

// ---------------------------------------------------------------------------
// Scratch: __device__ globals only (no allocations allowed anywhere).
// Ping-pong buffers hold w = dinv .* x in fp16 (uint2 = 4 halves per lane;
// 16 lanes per 64-dim node row = 128 B contiguous).
// INVARIANT: g_counts == 0 between kernel_launch calls. It is zero-initialized
// at module load, and scan_write_kernel re-zeros every element after use, so
// the invariant holds on the first call and on every graph replay.
// ---------------------------------------------------------------------------
__device__ uint2  g_bufA[MAX_N * 16];    // ping (w0, then w2)
__device__ uint2  g_bufB[MAX_N * 16];    // pong (w1)
__device__ float4 g_dinvs[MAX_N];        // (dinv, dinv^2, sqrt(deg), 0); 0s if isolated
__device__ int    g_counts[MAX_N];       // degree histogram (zero between calls)
__device__ int    g_offsets[MAX_N + 1];  // CSR row pointers (by dst)
__device__ int    g_pos[MAX_N];          // scatter cursors
__device__ int    g_src[MAX_E];          // CSR: source node per slot
__device__ int    g_blocksums[MAX_SCAN_BLOCKS];
__device__ int    g_blockoffs[MAX_SCAN_BLOCKS];

// ---------------------------------------------------------------------------
// 1) histogram of destinations (counts are zero on entry per invariant)
// ---------------------------------------------------------------------------
__global__ void count_kernel(const int* __restrict__ edge, int E) {
    int e = blockIdx.x * blockDim.x + threadIdx.x;
    if (e < E) atomicAdd(&g_counts[edge[E + e]], 1);
}

// ---------------------------------------------------------------------------
// 2) multi-block exclusive scan of counts -> offsets (3 phases)
//    Phase A also emits g_dinvs (counts already streaming here; one extra
//    rsqrt/sqrt + one coalesced float4 store per element).
// ---------------------------------------------------------------------------
__global__ __launch_bounds__(SCAN_TB)
void scan_partial_kernel(int n) {
    __shared__ int warp_sums[SCAN_TB / 32];
    const int base = blockIdx.x * SCAN_CHUNK;
    const int t = threadIdx.x;

    int s = 0;
    #pragma unroll
    for (int i = 0; i < SCAN_ITEMS; i++) {
        int idx = base + i * SCAN_TB + t;       // coalesced
        if (idx < n) {
            int c = g_counts[idx];
            s += c;
            float d  = (c > 0) ? rsqrtf((float)c) : 0.0f;
            float sd = (c > 0) ? sqrtf((float)c)  : 0.0f;
            g_dinvs[idx] = make_float4(d, d * d, sd, 0.0f);
        }
    }
    #pragma unroll
    for (int o = 16; o > 0; o >>= 1) s += __shfl_down_sync(0xffffffffu, s, o);
    if ((t & 31) == 0) warp_sums[t >> 5] = s;
    __syncthreads();
    if (t < SCAN_TB / 32) {
        int v = warp_sums[t];
        #pragma unroll
        for (int o = SCAN_TB / 64; o > 0; o >>= 1) v += __shfl_down_sync(0xffffffffu, v, o);
        if (t == 0) g_blocksums[blockIdx.x] = v;
    }
}

__global__ __launch_bounds__(MAX_SCAN_BLOCKS)
void scan_blocksums_kernel(int nb, int n, int E) {
    __shared__ int sh[MAX_SCAN_BLOCKS];
    const int t = threadIdx.x;
    sh[t] = (t < nb) ? g_blocksums[t] : 0;
    __syncthreads();
    #pragma unroll
    for (int off = 1; off < MAX_SCAN_BLOCKS; off <<= 1) {
        int v = (t >= off) ? sh[t - off] : 0;
        __syncthreads();
        sh[t] += v;
        __syncthreads();
    }
    if (t < nb) g_blockoffs[t] = (t == 0) ? 0 : sh[t - 1];
    if (t == 0) g_offsets[n] = E;
}

// Phase C also restores the g_counts == 0 invariant after consuming counts.
__global__ __launch_bounds__(SCAN_TB)
void scan_write_kernel(int n) {
    __shared__ int thread_sums[SCAN_TB];
    const int base = blockIdx.x * SCAN_CHUNK;
    const int t = threadIdx.x;
    const int lo = base + t * SCAN_ITEMS;

    int c[SCAN_ITEMS];
    int s = 0;
    #pragma unroll
    for (int i = 0; i < SCAN_ITEMS; i++) {
        int idx = lo + i;
        c[i] = (idx < n) ? g_counts[idx] : 0;
        s += c[i];
    }
    thread_sums[t] = s;
    __syncthreads();
    #pragma unroll
    for (int off = 1; off < SCAN_TB; off <<= 1) {
        int v = (t >= off) ? thread_sums[t - off] : 0;
        __syncthreads();
        thread_sums[t] += v;
        __syncthreads();
    }
    int prefix = g_blockoffs[blockIdx.x] + ((t == 0) ? 0 : thread_sums[t - 1]);
    #pragma unroll
    for (int i = 0; i < SCAN_ITEMS; i++) {
        int idx = lo + i;
        if (idx < n) {
            g_offsets[idx] = prefix;
            g_pos[idx]     = prefix;
            g_counts[idx]  = 0;                 // restore invariant for next call
            prefix += c[i];
        }
    }
}

// ---------------------------------------------------------------------------
// 3+4) fused: scatter edges into CSR slots AND init w0 (independent work;
//      both inputs (g_pos, g_dinvs) were produced by earlier kernels).
// ---------------------------------------------------------------------------
__global__ void fill_init_kernel(const int* __restrict__ edge, int E,
                                 const float* __restrict__ ue,
                                 const float* __restrict__ ie,
                                 int nu_elems, int total) {
    int i = blockIdx.x * blockDim.x + threadIdx.x;
    if (i < E) {
        int r = edge[i];
        int c = edge[E + i];
        int slot = atomicAdd(&g_pos[c], 1);
        g_src[slot] = r;
    }
    if (i < total) {
        float v = (i < nu_elems) ? ue[i] : ie[i - nu_elems];
        reinterpret_cast<__half*>(g_bufA)[i] = __float2half_rn(v * g_dinvs[i >> 6].x);
    }
}

// ---------------------------------------------------------------------------
// 5) pull pass: S[n] = sum_{k in csr(n)} W[src[k]]  (fp16 payload, fp32 accum)
//    MID:  Y[n] = fp16( dinv^2 * S )
//    LAST: out[n] = 0.25*( x0 + sqrtdeg*(w1+w2) + dinv*S )
//    16 threads (half-warp) per node, one uint2 (4 halves) lane each;
//    2-edge unroll with dual accumulators (proven R9 loop).
// ---------------------------------------------------------------------------
__device__ __forceinline__ void acc_u2(const uint2 u, float& x, float& y, float& z, float& w) {
    float2 f0 = __half22float2(*reinterpret_cast<const __half2*>(&u.x));
    float2 f1 = __half22float2(*reinterpret_cast<const __half2*>(&u.y));
    x += f0.x; y += f0.y; z += f1.x; w += f1.y;
}

template <bool A_TO_B, bool LAST>
__global__ __launch_bounds__(256)
void pull_kernel(int N, int nu_nodes,
                 const float* __restrict__ ue, const float* __restrict__ ie,
                 float* __restrict__ out) {
    int t = blockIdx.x * blockDim.x + threadIdx.x;
    int node = t >> 4;
    if (node >= N) return;
    int lane = t & 15;

    const uint2* __restrict__ X = A_TO_B ? g_bufA : g_bufB;
    uint2*       __restrict__ Y = A_TO_B ? g_bufB : g_bufA;

    const int beg = g_offsets[node];
    const int end = g_offsets[node + 1];

    float a0x = 0.f, a0y = 0.f, a0z = 0.f, a0w = 0.f;
    float a1x = 0.f, a1y = 0.f, a1z = 0.f, a1w = 0.f;

    int k = beg;
    for (; k + 1 < end; k += 2) {
        int s0 = g_src[k];
        int s1 = g_src[k + 1];
        uint2 u0 = X[(size_t)s0 * 16 + lane];
        uint2 u1 = X[(size_t)s1 * 16 + lane];
        acc_u2(u0, a0x, a0y, a0z, a0w);
        acc_u2(u1, a1x, a1y, a1z, a1w);
    }
    if (k < end) {
        uint2 u0 = X[(size_t)g_src[k] * 16 + lane];
        acc_u2(u0, a0x, a0y, a0z, a0w);
    }

    float sx = a0x + a1x, sy = a0y + a1y, sz = a0z + a1z, sw = a0w + a1w;

    float4 dv = g_dinvs[node];          // (dinv, dinv^2, sqrtdeg, 0)

    if (!LAST) {
        __half2 p0 = __floats2half2_rn(dv.y * sx, dv.y * sy);
        __half2 p1 = __floats2half2_rn(dv.y * sz, dv.y * sw);
        uint2 st;
        st.x = *reinterpret_cast<unsigned int*>(&p0);
        st.y = *reinterpret_cast<unsigned int*>(&p1);
        Y[(size_t)node * 16 + lane] = st;
    } else {
        // x0 from inputs; w1 in bufB, w2 in bufA (== X for this launch)
        const float* x0row = (node < nu_nodes)
            ? (ue + (size_t)node * DIM)
            : (ie + (size_t)(node - nu_nodes) * DIM);
        float4 x0 = *reinterpret_cast<const float4*>(x0row + (lane << 2));

        uint2 u1 = g_bufB[(size_t)node * 16 + lane];
        uint2 u2 = g_bufA[(size_t)node * 16 + lane];
        float w1x = 0.f, w1y = 0.f, w1z = 0.f, w1w = 0.f;
        float w2x = 0.f, w2y = 0.f, w2z = 0.f, w2w = 0.f;
        acc_u2(u1, w1x, w1y, w1z, w1w);
        acc_u2(u2, w2x, w2y, w2z, w2w);

        float4 r;
        r.x = 0.25f * (x0.x + dv.z * (w1x + w2x) + dv.x * sx);
        r.y = 0.25f * (x0.y + dv.z * (w1y + w2y) + dv.x * sy);
        r.z = 0.25f * (x0.z + dv.z * (w1z + w2z) + dv.x * sz);
        r.w = 0.25f * (x0.w + dv.z * (w1w + w2w) + dv.x * sw);
        *reinterpret_cast<float4*>(out + (size_t)node * DIM + (lane << 2)) = r;
    }
}

// ---------------------------------------------------------------------------
// kernel_launch
// inputs: [0] user_emb f32 [100000*64], [1] item_emb f32 [50000*64],
//         [2] edge_index int32 [2 * 1200000]
// output: f32 [150000*64]
// ---------------------------------------------------------------------------
extern "C" void kernel_launch(void* const* d_in, const int* in_sizes, int n_in,
                              void* d_out, int out_size) {
    const float* user_emb = (const float*)d_in[0];
    const float* item_emb = (const float*)d_in[1];
    const int*   edge     = (const int*)d_in[2];
    float*       out      = (float*)d_out;

    const int nu_elems = in_sizes[0];
    const int ni_elems = in_sizes[1];
    const int E        = in_sizes[2] / 2;
    const int NU       = nu_elems / DIM;
    const int N        = NU + ni_elems / DIM;
    const int total    = N * DIM;

    const int TB = 256;
    const int eblk  = (E + TB - 1) / TB;
    const int tblk  = (total + TB - 1) / TB;     // total > E, covers both fused loops
    const int pullb = (N * 16 + TB - 1) / TB;
    const int scanb = (N + SCAN_CHUNK - 1) / SCAN_CHUNK;

    // CSR build (by destination); counts arrive zero per the self-clean invariant
    count_kernel<<<eblk, TB>>>(edge, E);
    scan_partial_kernel<<<scanb, SCAN_TB>>>(N);            // + g_dinvs
    scan_blocksums_kernel<<<1, MAX_SCAN_BLOCKS>>>(scanb, N, E);
    scan_write_kernel<<<scanb, SCAN_TB>>>(N);
    fill_init_kernel<<<tblk, TB>>>(edge, E, user_emb, item_emb, nu_elems, total);

    // 3 propagation layers; out materialized only in the last one
    pull_kernel<true , false><<<pullb, TB>>>(N, NU, user_emb, item_emb, out); // A->B (w1)
    pull_kernel<false, false><<<pullb, TB>>>(N, NU, user_emb, item_emb, out); // B->A (w2)
    pull_kernel<true , true ><<<pullb, TB>>>(N, NU, user_emb, item_emb, out); // A-> out
}